// round 2
// baseline (speedup 1.0000x reference)
#include <cuda_runtime.h>
#include <cuda.h>
#include <cuda_bf16.h>
#include <cstdint>

// tcgen05 is only legal in the arch-specific (sm_103a / sm_100a) compilation
// pass. The harness also runs a plain sm_103 pass where those instructions are
// rejected by ptxas — so every tcgen05 usage is preprocessor-gated, with a
// correct (slow) SIMT fallback body for the non-'a' pass.
#if !defined(__CUDA_ARCH__)
#  define TC_ON 1   // host pass: parse the tcgen05 branch (not codegen'd)
#elif defined(__CUDA_ARCH_FEAT_SM103_ALL) || defined(__CUDA_ARCH_FEAT_SM100_ALL) || defined(__CUDA_ARCH_FEAT_SM101_ALL)
#  define TC_ON 1
#else
#  define TC_ON 0
#endif

// Problem dims
static constexpr int Bdim = 4096;
static constexpr int Mdim = 12893;
static constexpr int Ddim = 2048;

// GEMM tiling
static constexpr int BM = 128, BN = 128, BK = 64;
static constexpr int STAGES = 4;
static constexpr int KITERS = Ddim / BK;            // 32
static constexpr int STAGE_BYTES = BM * 128;        // 16 KB per operand stage (128 rows x 128B)
static constexpr int SMEM_A_OFF = 0;
static constexpr int SMEM_B_OFF = STAGES * STAGE_BYTES;        // 65536
static constexpr int SMEM_BAR_OFF = 2 * STAGES * STAGE_BYTES;  // 131072
static constexpr int SMEM_TMEMPTR_OFF = SMEM_BAR_OFF + 80;
static constexpr int SMEM_TOTAL = SMEM_BAR_OFF + 128;          // 131200

// idesc for kind::f16: dtype=F32(1<<4), atype=BF16(1<<7), btype=BF16(1<<10),
// N/8 << 17, M/16 << 24  (validated against example constant 0x8080490 for M=128,N=32)
static constexpr uint32_t MMA_IDESC =
    (1u << 4) | (1u << 7) | (1u << 10) | ((BN / 8) << 17) | ((BM / 16) << 24);

// bf16 normalized scratch (device globals: allocation-free rule)
__device__ __nv_bfloat16 g_xn[(size_t)Bdim * Ddim];
__device__ __nv_bfloat16 g_pn[(size_t)Mdim * Ddim];

// ---------------- PTX helpers (arch-portable ones) ----------------
__device__ __forceinline__ uint32_t smem_u32(const void* p) {
    uint32_t a;
    asm("{ .reg .u64 t; cvta.to.shared.u64 t, %1; cvt.u32.u64 %0, t; }" : "=r"(a) : "l"(p));
    return a;
}
__device__ __forceinline__ uint32_t elect_one() {
    uint32_t p;
    asm volatile("{\n\t.reg .pred p;\n\telect.sync _|p, 0xFFFFFFFF;\n\tselp.b32 %0, 1, 0, p;\n\t}" : "=r"(p));
    return p;
}

#define MBARRIER_INIT(addr, count) \
    asm volatile("mbarrier.init.shared.b64 [%0], %1;" :: "r"((uint32_t)(addr)), "r"((uint32_t)(count)) : "memory")

#define MBARRIER_EXPECT_TX(addr, bytes) \
    asm volatile("mbarrier.arrive.expect_tx.shared.b64 _, [%0], %1;" :: "r"((uint32_t)(addr)), "r"((uint32_t)(bytes)) : "memory")

#define MBARRIER_WAIT_PARITY(mbar_smem_addr, phase_parity) do { \
    uint32_t _mbar = (uint32_t)(mbar_smem_addr); \
    uint32_t _parity = (uint32_t)(phase_parity); \
    uint32_t _done; \
    asm volatile( \
        "{\n\t.reg .pred p;\n\t" \
        "mbarrier.try_wait.parity.acquire.cta.shared::cta.b64 p, [%1], %2;\n\t" \
        "selp.b32 %0, 1, 0, p;\n\t}" \
        : "=r"(_done) : "r"(_mbar), "r"(_parity) : "memory"); \
    if (!_done) { \
        asm volatile( \
            "{\n\t.reg .pred P1;\n\t" \
            "WAIT_LOOP_%=:\n\t" \
            "mbarrier.try_wait.parity.acquire.cta.shared::cta.b64 P1, [%0], %1, 0x989680;\n\t" \
            "@P1 bra.uni WAIT_DONE_%=;\n\t" \
            "bra.uni WAIT_LOOP_%=;\n\t" \
            "WAIT_DONE_%=:\n\t}" \
            :: "r"(_mbar), "r"(_parity) : "memory"); \
    } \
} while(0)

#define MBARRIER_WAIT_PARITY_RELAXED(mbar_smem_addr, phase_parity) do { \
    uint32_t _mbar = (uint32_t)(mbar_smem_addr); \
    uint32_t _parity = (uint32_t)(phase_parity); \
    uint32_t _done; \
    asm volatile( \
        "{\n\t.reg .pred p;\n\t" \
        "mbarrier.try_wait.parity.relaxed.cta.shared::cta.b64 p, [%1], %2, 0x989680;\n\t" \
        "selp.b32 %0, 1, 0, p;\n\t}" \
        : "=r"(_done) : "r"(_mbar), "r"(_parity) : "memory"); \
    if (!_done) { \
        asm volatile( \
            "{\n\t.reg .pred P1;\n\t" \
            "WAIT_LOOP_%=:\n\t" \
            "mbarrier.try_wait.parity.relaxed.cta.shared::cta.b64 P1, [%0], %1, 0x989680;\n\t" \
            "@P1 bra.uni WAIT_DONE_%=;\n\t" \
            "bra.uni WAIT_LOOP_%=;\n\t" \
            "WAIT_DONE_%=:\n\t}" \
            :: "r"(_mbar), "r"(_parity) : "memory"); \
    } \
} while(0)

__device__ __forceinline__ void tma_load_2d(uint32_t smem_addr, const void* tm,
                                            int cx, int cy, uint32_t mbar) {
    asm volatile(
        "cp.async.bulk.tensor.2d.shared::cta.global.tile.mbarrier::complete_tx::bytes "
        "[%0], [%1, {%2, %3}], [%4];"
        :: "r"(smem_addr), "l"(tm), "r"(cx), "r"(cy), "r"(mbar) : "memory");
}

// ---------------- tcgen05-only helpers (sm_103a pass only) ----------------
#if TC_ON
#define TCGEN05_ALLOC(smem_result_addr, nCols) \
    asm volatile("tcgen05.alloc.cta_group::1.sync.aligned.shared::cta.b32 [%0], %1;" \
        :: "r"((uint32_t)(smem_result_addr)), "r"((uint32_t)(nCols)) : "memory")
#define TCGEN05_DEALLOC(tmem_addr, nCols) \
    asm volatile("tcgen05.dealloc.cta_group::1.sync.aligned.b32 %0, %1;" :: "r"(tmem_addr), "r"((uint32_t)(nCols)))
#define TCGEN05_RELINQUISH_ALLOC_PERMIT() \
    asm volatile("tcgen05.relinquish_alloc_permit.cta_group::1.sync.aligned;")
#define TCGEN05_COMMIT(mbar_smem_addr) \
    asm volatile("tcgen05.commit.cta_group::1.mbarrier::arrive::one.shared::cluster.b64 [%0];" \
        :: "r"((uint32_t)(mbar_smem_addr)) : "memory")
#define TCGEN05_FENCE_BEFORE() asm volatile("tcgen05.fence::before_thread_sync;" ::: "memory")
#define TCGEN05_FENCE_AFTER()  asm volatile("tcgen05.fence::after_thread_sync;" ::: "memory")
#define TCGEN05_WAIT_LD()      asm volatile("tcgen05.wait::ld.sync.aligned;" ::: "memory")

#define TCGEN05_LD_32X32B_X32(r, tmem_addr) \
    asm volatile( \
        "tcgen05.ld.sync.aligned.32x32b.x32.b32 " \
        "{%0, %1, %2, %3, %4, %5, %6, %7, " \
        " %8, %9, %10, %11, %12, %13, %14, %15, " \
        " %16, %17, %18, %19, %20, %21, %22, %23, " \
        " %24, %25, %26, %27, %28, %29, %30, %31}, [%32];" \
        : "=r"((r)[0]),  "=r"((r)[1]),  "=r"((r)[2]),  "=r"((r)[3]), \
          "=r"((r)[4]),  "=r"((r)[5]),  "=r"((r)[6]),  "=r"((r)[7]), \
          "=r"((r)[8]),  "=r"((r)[9]),  "=r"((r)[10]), "=r"((r)[11]), \
          "=r"((r)[12]), "=r"((r)[13]), "=r"((r)[14]), "=r"((r)[15]), \
          "=r"((r)[16]), "=r"((r)[17]), "=r"((r)[18]), "=r"((r)[19]), \
          "=r"((r)[20]), "=r"((r)[21]), "=r"((r)[22]), "=r"((r)[23]), \
          "=r"((r)[24]), "=r"((r)[25]), "=r"((r)[26]), "=r"((r)[27]), \
          "=r"((r)[28]), "=r"((r)[29]), "=r"((r)[30]), "=r"((r)[31]) \
        : "r"(tmem_addr))

// SW128 K-major SMEM descriptor (Blackwell): LBO=1, SBO=64, version=1, layout=SW128
static constexpr uint64_t SMEM_DESC_BASE_SW128 =
    (uint64_t(2) << 61) | (uint64_t(1) << 46) | (uint64_t(64) << 32) | (uint64_t(1) << 16);
#define MAKE_SMEM_DESC(base_addr) (SMEM_DESC_BASE_SW128 | ((uint64_t)((base_addr) >> 4) & 0x3FFF))

// SS-mode cg1 bf16 MMA (A desc, B desc), fp32 accum
__device__ __forceinline__ void mma_f16_ss_cg1(uint32_t d_tmem, uint64_t a_desc, uint64_t b_desc,
                                               uint32_t idesc, bool acc) {
    uint32_t en = acc ? 1u : 0u;
    asm volatile(
        "{\n\t.reg .pred p;\n\t"
        "setp.ne.u32 p, %5, 0;\n\t"
        "tcgen05.mma.cta_group::1.kind::f16 [%0], %1, %2, %3, {%4, %4, %4, %4}, p;\n\t"
        "}"
        :: "r"(d_tmem), "l"(a_desc), "l"(b_desc), "r"(idesc), "r"(0u), "r"(en)
        : "memory");
}
#endif  // TC_ON

// ---------------- Row L2-normalize fp32 -> bf16 ----------------
__global__ __launch_bounds__(256) void normalize_rows_kernel(
    const float* __restrict__ in, __nv_bfloat16* __restrict__ out) {
    int row = blockIdx.x;
    const float4* r4 = reinterpret_cast<const float4*>(in + (size_t)row * Ddim);
    __shared__ float red[8];
    float4 v[2];
    float ss = 0.f;
#pragma unroll
    for (int i = 0; i < 2; i++) {
        v[i] = r4[threadIdx.x + i * 256];
        ss = fmaf(v[i].x, v[i].x, ss);
        ss = fmaf(v[i].y, v[i].y, ss);
        ss = fmaf(v[i].z, v[i].z, ss);
        ss = fmaf(v[i].w, v[i].w, ss);
    }
#pragma unroll
    for (int o = 16; o; o >>= 1) ss += __shfl_xor_sync(0xffffffffu, ss, o);
    if ((threadIdx.x & 31) == 0) red[threadIdx.x >> 5] = ss;
    __syncthreads();
    float tot = 0.f;
#pragma unroll
    for (int i = 0; i < 8; i++) tot += red[i];
    float inv = 1.0f / fmaxf(sqrtf(tot), 1e-12f);
    uint2* o2 = reinterpret_cast<uint2*>(out + (size_t)row * Ddim);
#pragma unroll
    for (int i = 0; i < 2; i++) {
        int c = threadIdx.x + i * 256;
        __nv_bfloat162 lo = __float22bfloat162_rn(make_float2(v[i].x * inv, v[i].y * inv));
        __nv_bfloat162 hi = __float22bfloat162_rn(make_float2(v[i].z * inv, v[i].w * inv));
        uint2 pk;
        pk.x = *reinterpret_cast<uint32_t*>(&lo);
        pk.y = *reinterpret_cast<uint32_t*>(&hi);
        o2[c] = pk;
    }
}

// ---------------- GEMM + epilogue kernel ----------------
__global__ __launch_bounds__(256, 1) void isomax_gemm_kernel(
    const __grid_constant__ CUtensorMap tmA,
    const __grid_constant__ CUtensorMap tmB,
    const __nv_bfloat16* __restrict__ An,   // raw pointers for fallback path
    const __nv_bfloat16* __restrict__ Bn,
    const float* __restrict__ scale_ptr,
    float* __restrict__ out) {
#if TC_ON
    // =================== tcgen05 path (sm_103a) ===================
    extern __shared__ char smem[];
    uint32_t sb = smem_u32(smem);
    int tid = threadIdx.x, wid = tid >> 5, lid = tid & 31;
    int tile_n = blockIdx.x, tile_m = blockIdx.y;

    uint32_t bar_full0  = sb + SMEM_BAR_OFF;        // 4 x 8B
    uint32_t bar_empty0 = sb + SMEM_BAR_OFF + 32;   // 4 x 8B
    uint32_t bar_done   = sb + SMEM_BAR_OFF + 64;

    if (wid == 0) TCGEN05_ALLOC(sb + SMEM_TMEMPTR_OFF, 128);
    if (tid == 0) {
#pragma unroll
        for (int s = 0; s < STAGES; s++) {
            MBARRIER_INIT(bar_full0 + s * 8, 1);
            MBARRIER_INIT(bar_empty0 + s * 8, 1);
        }
        MBARRIER_INIT(bar_done, 1);
    }
    __syncthreads();

    uint32_t tmem;
    asm volatile("ld.shared.b32 %0, [%1];" : "=r"(tmem) : "r"(sb + SMEM_TMEMPTR_OFF));

    if (wid == 1 && elect_one()) {
        // ---- TMA producer ----
        int phase = 1;  // fresh barriers: parity-1 wait passes immediately
        for (int s = 0; s < KITERS; s++) {
            int slot = s & (STAGES - 1);
            MBARRIER_WAIT_PARITY_RELAXED(bar_empty0 + slot * 8, phase);
            MBARRIER_EXPECT_TX(bar_full0 + slot * 8, 2 * STAGE_BYTES);
            tma_load_2d(sb + SMEM_A_OFF + slot * STAGE_BYTES, &tmA,
                        s * BK, tile_m * BM, bar_full0 + slot * 8);
            tma_load_2d(sb + SMEM_B_OFF + slot * STAGE_BYTES, &tmB,
                        s * BK, tile_n * BN, bar_full0 + slot * 8);
            if (slot == STAGES - 1) phase ^= 1;
        }
    } else if (wid == 0 && elect_one()) {
        // ---- MMA consumer ----
        int phase = 0;
        for (int s = 0; s < KITERS; s++) {
            int slot = s & (STAGES - 1);
            MBARRIER_WAIT_PARITY(bar_full0 + slot * 8, phase);
            uint64_t ad = MAKE_SMEM_DESC(sb + SMEM_A_OFF + slot * STAGE_BYTES);
            uint64_t bd = MAKE_SMEM_DESC(sb + SMEM_B_OFF + slot * STAGE_BYTES);
#pragma unroll
            for (int k = 0; k < BK / 16; k++) {
                mma_f16_ss_cg1(tmem, ad + k * 2, bd + k * 2, MMA_IDESC, (s | k) != 0);
            }
            TCGEN05_COMMIT(bar_empty0 + slot * 8);
            if (slot == STAGES - 1) phase ^= 1;
        }
        TCGEN05_COMMIT(bar_done);
    }

    __syncthreads();
    MBARRIER_WAIT_PARITY(bar_done, 0);
    TCGEN05_FENCE_AFTER();

    // ---- Epilogue: TMEM -> regs -> math -> SMEM transpose -> coalesced STG ----
    float sgn = fabsf(scale_ptr[0]);
    int sub  = wid & 3;   // TMEM subpartition (rows sub*32 + lid)
    int half = wid >> 2;  // warps 0-3 cols [0,64), warps 4-7 cols [64,128)

    uint32_t regs[64];
    TCGEN05_LD_32X32B_X32(regs, tmem + half * 64);
    TCGEN05_LD_32X32B_X32(regs + 32, tmem + half * 64 + 32);
    TCGEN05_WAIT_LD();
    TCGEN05_FENCE_BEFORE();

    float* tile = reinterpret_cast<float*>(smem);  // reuse stage SMEM; stride 129
    int row = sub * 32 + lid;
#pragma unroll
    for (int c = 0; c < 64; c++) {
        float v = __uint_as_float(regs[c]);
        float d2 = fmaxf(2.0f - 2.0f * v, 0.0f);
        tile[row * 129 + half * 64 + c] = -sgn * sqrtf(d2);
    }
    __syncthreads();

    int gm0 = tile_m * BM;
    int gn0 = tile_n * BN;
#pragma unroll 4
    for (int it = 0; it < (BM * BN) / 256; it++) {
        int idx = it * 256 + tid;
        int m = idx >> 7;
        int n = idx & 127;
        int gn = gn0 + n;
        if (gn < Mdim)
            out[(size_t)(gm0 + m) * Mdim + gn] = tile[m * 129 + n];
    }

    __syncthreads();
    if (wid == 0) {
        TCGEN05_RELINQUISH_ALLOC_PERMIT();
        TCGEN05_DEALLOC(tmem, 128);
    }
#else
    // =================== SIMT fallback (non-'a' pass; correctness insurance) ===================
    extern __shared__ char smem[];
    constexpr int LDT = 72;  // padded bf16 row stride (16B aligned)
    __nv_bfloat16* sA = reinterpret_cast<__nv_bfloat16*>(smem);          // [2][128*LDT]
    __nv_bfloat16* sB = sA + 2 * 128 * LDT;                              // [2][128*LDT]

    int tid = threadIdx.x;
    int tx = tid & 15, ty = tid >> 4;              // 16x16 threads, 8x8 each
    int tile_n = blockIdx.x, tile_m = blockIdx.y;
    int gm0 = tile_m * BM, gn0 = tile_n * BN;

    float acc[8][8];
#pragma unroll
    for (int i = 0; i < 8; i++)
#pragma unroll
        for (int j = 0; j < 8; j++) acc[i][j] = 0.f;

    auto load_stage = [&](int s, int buf) {
        int k0 = s * BK;
#pragma unroll
        for (int i = 0; i < 4; i++) {
            int v = tid + 256 * i;           // 1024 vec8 per operand
            int r = v >> 3, c8 = (v & 7) * 8;
            // A
            const uint4* srcA = reinterpret_cast<const uint4*>(An + (size_t)(gm0 + r) * Ddim + k0 + c8);
            *reinterpret_cast<uint4*>(sA + buf * 128 * LDT + r * LDT + c8) = *srcA;
            // B (clamp OOB rows; results masked at store)
            int br = gn0 + r; if (br >= Mdim) br = Mdim - 1;
            const uint4* srcB = reinterpret_cast<const uint4*>(Bn + (size_t)br * Ddim + k0 + c8);
            *reinterpret_cast<uint4*>(sB + buf * 128 * LDT + r * LDT + c8) = *srcB;
        }
    };

    load_stage(0, 0);
    __syncthreads();
    for (int s = 0; s < KITERS; s++) {
        int buf = s & 1;
        if (s + 1 < KITERS) load_stage(s + 1, buf ^ 1);
        const __nv_bfloat16* a0 = sA + buf * 128 * LDT;
        const __nv_bfloat16* b0 = sB + buf * 128 * LDT;
#pragma unroll 8
        for (int kk = 0; kk < BK; kk++) {
            float ar[8], br[8];
#pragma unroll
            for (int i = 0; i < 8; i++) ar[i] = __bfloat162float(a0[(ty * 8 + i) * LDT + kk]);
#pragma unroll
            for (int j = 0; j < 8; j++) br[j] = __bfloat162float(b0[(tx * 8 + j) * LDT + kk]);
#pragma unroll
            for (int i = 0; i < 8; i++)
#pragma unroll
                for (int j = 0; j < 8; j++) acc[i][j] = fmaf(ar[i], br[j], acc[i][j]);
        }
        __syncthreads();
    }

    float sgn = fabsf(scale_ptr[0]);
#pragma unroll
    for (int i = 0; i < 8; i++) {
        int gm = gm0 + ty * 8 + i;
#pragma unroll
        for (int j = 0; j < 8; j++) {
            int gn = gn0 + tx * 8 + j;
            if (gn < Mdim) {
                float d2 = fmaxf(2.0f - 2.0f * acc[i][j], 0.0f);
                out[(size_t)gm * Mdim + gn] = -sgn * sqrtf(d2);
            }
        }
    }
#endif
}

// ---------------- host launch ----------------
typedef CUresult (*PFN_tmEncode)(
    CUtensorMap*, CUtensorMapDataType, cuuint32_t, void*,
    const cuuint64_t*, const cuuint64_t*, const cuuint32_t*, const cuuint32_t*,
    CUtensorMapInterleave, CUtensorMapSwizzle, CUtensorMapL2promotion, CUtensorMapFloatOOBfill);

extern "C" void kernel_launch(void* const* d_in, const int* in_sizes, int n_in,
                              void* d_out, int out_size) {
    const float* x      = (const float*)d_in[0];
    const float* protos = (const float*)d_in[1];
    const float* dscale = (const float*)d_in[2];
    float* out = (float*)d_out;

    void *pA = nullptr, *pB = nullptr;
    cudaGetSymbolAddress(&pA, g_xn);
    cudaGetSymbolAddress(&pB, g_pn);

    normalize_rows_kernel<<<Bdim, 256>>>(x, (__nv_bfloat16*)pA);
    normalize_rows_kernel<<<Mdim, 256>>>(protos, (__nv_bfloat16*)pB);

    // TMA tensor maps (host-side encode; capture-legal, no stream ops)
    void* fp = nullptr;
    cudaDriverEntryPointQueryResult qr;
    cudaGetDriverEntryPoint("cuTensorMapEncodeTiled", &fp, cudaEnableDefault, &qr);
    PFN_tmEncode enc = (PFN_tmEncode)fp;

    CUtensorMap tmA{}, tmB{};
    {
        cuuint64_t dims[2]    = {(cuuint64_t)Ddim, (cuuint64_t)Bdim};
        cuuint64_t strides[1] = {(cuuint64_t)Ddim * sizeof(__nv_bfloat16)};
        cuuint32_t box[2]     = {(cuuint32_t)BK, (cuuint32_t)BM};  // 64 bf16 = 128B rows
        cuuint32_t es[2]      = {1, 1};
        enc(&tmA, CU_TENSOR_MAP_DATA_TYPE_BFLOAT16, 2, pA, dims, strides, box, es,
            CU_TENSOR_MAP_INTERLEAVE_NONE, CU_TENSOR_MAP_SWIZZLE_128B,
            CU_TENSOR_MAP_L2_PROMOTION_L2_128B, CU_TENSOR_MAP_FLOAT_OOB_FILL_NONE);
    }
    {
        cuuint64_t dims[2]    = {(cuuint64_t)Ddim, (cuuint64_t)Mdim};
        cuuint64_t strides[1] = {(cuuint64_t)Ddim * sizeof(__nv_bfloat16)};
        cuuint32_t box[2]     = {(cuuint32_t)BK, (cuuint32_t)BN};
        cuuint32_t es[2]      = {1, 1};
        enc(&tmB, CU_TENSOR_MAP_DATA_TYPE_BFLOAT16, 2, pB, dims, strides, box, es,
            CU_TENSOR_MAP_INTERLEAVE_NONE, CU_TENSOR_MAP_SWIZZLE_128B,
            CU_TENSOR_MAP_L2_PROMOTION_L2_128B, CU_TENSOR_MAP_FLOAT_OOB_FILL_NONE);
    }

    cudaFuncSetAttribute(isomax_gemm_kernel,
                         cudaFuncAttributeMaxDynamicSharedMemorySize, SMEM_TOTAL);
    dim3 grid((Mdim + BN - 1) / BN, Bdim / BM);  // (101, 32)
    isomax_gemm_kernel<<<grid, 256, SMEM_TOTAL>>>(
        tmA, tmB, (const __nv_bfloat16*)pA, (const __nv_bfloat16*)pB, dscale, out);
}

// round 6
// speedup vs baseline: 1.3186x; 1.3186x over previous
#include <cuda_runtime.h>
#include <cuda.h>
#include <cuda_bf16.h>
#include <cstdint>

// tcgen05 (and TMA multicast) only in the arch-specific pass; plain sm_103
// pass gets a correct SIMT fallback.
#if !defined(__CUDA_ARCH__)
#  define TC_ON 1
#elif defined(__CUDA_ARCH_FEAT_SM103_ALL) || defined(__CUDA_ARCH_FEAT_SM100_ALL) || defined(__CUDA_ARCH_FEAT_SM101_ALL)
#  define TC_ON 1
#else
#  define TC_ON 0
#endif

// Problem dims
static constexpr int Bdim = 4096;
static constexpr int Mdim = 12893;
static constexpr int Ddim = 2048;

// Tiling: per-CTA output 128(m) x 256(n); cluster of 2 CTAs pairs adjacent m
// tiles sharing the SAME B tile via TMA multicast (cooperative slicing).
static constexpr int BM = 128, BN = 256, BK = 64;
static constexpr int STAGES = 3;
static constexpr int KITERS = Ddim / BK;            // 32
static constexpr int STAGE_A = BM * 128;            // 16384
static constexpr int STAGE_B = BN * 128;            // 32768
static constexpr int STAGE_BYTES = STAGE_A + STAGE_B;   // 49152
static constexpr int SMEM_BAR_OFF = STAGES * STAGE_BYTES;   // 147456
//   full[3] @ +0, empty[3] @ +24, mma_done[2] @ +48, epi_free[2] @ +64, tmemptr @ +96
static constexpr int SMEM_TRANS_OFF = SMEM_BAR_OFF + 128;   // 147584
static constexpr int SMEM_TOTAL = SMEM_TRANS_OFF + 128 * 129 * 4;  // 213,632

// Tile grid
static constexpr int NSUP = (Mdim + BN - 1) / BN;   // 51
static constexpr int MSUP = Bdim / (2 * BM);        // 16 (m pairs)
static constexpr int TOT_TILES = NSUP * MSUP;       // 816
static constexpr int NCLUSTERS = 74;                // 148 CTAs / 2

static constexpr int THREADS = 320;                 // w0-7 epi, w8 mma, w9 tma

// idesc kind::f16 bf16/bf16 fp32-acc, M=128, N=128 (two N=128 MMAs per chunk)
static constexpr uint32_t MMA_IDESC =
    (1u << 4) | (1u << 7) | (1u << 10) | ((128 / 8) << 17) | ((BM / 16) << 24);

__device__ __nv_bfloat16 g_xn[(size_t)Bdim * Ddim];
__device__ __nv_bfloat16 g_pn[(size_t)Mdim * Ddim];

// ---------------- portable PTX helpers ----------------
__device__ __forceinline__ uint32_t smem_u32(const void* p) {
    uint32_t a;
    asm("{ .reg .u64 t; cvta.to.shared.u64 t, %1; cvt.u32.u64 %0, t; }" : "=r"(a) : "l"(p));
    return a;
}
__device__ __forceinline__ uint32_t elect_one() {
    uint32_t p;
    asm volatile("{\n\t.reg .pred p;\n\telect.sync _|p, 0xFFFFFFFF;\n\tselp.b32 %0, 1, 0, p;\n\t}" : "=r"(p));
    return p;
}

#define MBARRIER_INIT(addr, count) \
    asm volatile("mbarrier.init.shared.b64 [%0], %1;" :: "r"((uint32_t)(addr)), "r"((uint32_t)(count)) : "memory")
#define MBARRIER_EXPECT_TX(addr, bytes) \
    asm volatile("mbarrier.arrive.expect_tx.shared.b64 _, [%0], %1;" :: "r"((uint32_t)(addr)), "r"((uint32_t)(bytes)) : "memory")
#define MBARRIER_ARRIVE(addr) \
    asm volatile("mbarrier.arrive.shared.b64 _, [%0];" :: "r"((uint32_t)(addr)) : "memory")

#define MBARRIER_WAIT_PARITY(mbar_smem_addr, phase_parity) do { \
    uint32_t _mbar = (uint32_t)(mbar_smem_addr); \
    uint32_t _parity = (uint32_t)(phase_parity); \
    uint32_t _done; \
    asm volatile( \
        "{\n\t.reg .pred p;\n\t" \
        "mbarrier.try_wait.parity.acquire.cta.shared::cta.b64 p, [%1], %2;\n\t" \
        "selp.b32 %0, 1, 0, p;\n\t}" \
        : "=r"(_done) : "r"(_mbar), "r"(_parity) : "memory"); \
    if (!_done) { \
        asm volatile( \
            "{\n\t.reg .pred P1;\n\t" \
            "WAIT_LOOP_%=:\n\t" \
            "mbarrier.try_wait.parity.acquire.cta.shared::cta.b64 P1, [%0], %1, 0x989680;\n\t" \
            "@P1 bra.uni WAIT_DONE_%=;\n\t" \
            "bra.uni WAIT_LOOP_%=;\n\t" \
            "WAIT_DONE_%=:\n\t}" \
            :: "r"(_mbar), "r"(_parity) : "memory"); \
    } \
} while(0)

#define MBARRIER_WAIT_PARITY_RELAXED(mbar_smem_addr, phase_parity) do { \
    uint32_t _mbar = (uint32_t)(mbar_smem_addr); \
    uint32_t _parity = (uint32_t)(phase_parity); \
    uint32_t _done; \
    asm volatile( \
        "{\n\t.reg .pred p;\n\t" \
        "mbarrier.try_wait.parity.relaxed.cta.shared::cta.b64 p, [%1], %2, 0x989680;\n\t" \
        "selp.b32 %0, 1, 0, p;\n\t}" \
        : "=r"(_done) : "r"(_mbar), "r"(_parity) : "memory"); \
    if (!_done) { \
        asm volatile( \
            "{\n\t.reg .pred P1;\n\t" \
            "WAIT_LOOP_%=:\n\t" \
            "mbarrier.try_wait.parity.relaxed.cta.shared::cta.b64 P1, [%0], %1, 0x989680;\n\t" \
            "@P1 bra.uni WAIT_DONE_%=;\n\t" \
            "bra.uni WAIT_LOOP_%=;\n\t" \
            "WAIT_DONE_%=:\n\t}" \
            :: "r"(_mbar), "r"(_parity) : "memory"); \
    } \
} while(0)

#define CLUSTER_SYNC() do { \
    asm volatile("barrier.cluster.arrive.aligned;" ::: "memory"); \
    asm volatile("barrier.cluster.wait.aligned;" ::: "memory"); \
} while(0)

// ---------------- tcgen05 / multicast helpers (arch-specific pass) ----------------
#if TC_ON
#define TCGEN05_ALLOC(smem_result_addr, nCols) \
    asm volatile("tcgen05.alloc.cta_group::1.sync.aligned.shared::cta.b32 [%0], %1;" \
        :: "r"((uint32_t)(smem_result_addr)), "r"((uint32_t)(nCols)) : "memory")
#define TCGEN05_DEALLOC(tmem_addr, nCols) \
    asm volatile("tcgen05.dealloc.cta_group::1.sync.aligned.b32 %0, %1;" :: "r"(tmem_addr), "r"((uint32_t)(nCols)))
#define TCGEN05_RELINQUISH_ALLOC_PERMIT() \
    asm volatile("tcgen05.relinquish_alloc_permit.cta_group::1.sync.aligned;")
#define TCGEN05_COMMIT(mbar) \
    asm volatile("tcgen05.commit.cta_group::1.mbarrier::arrive::one.shared::cluster.b64 [%0];" \
        :: "r"((uint32_t)(mbar)) : "memory")
#define TCGEN05_COMMIT_MC(mbar, mask) \
    asm volatile("tcgen05.commit.cta_group::1.mbarrier::arrive::one.shared::cluster.multicast::cluster.b64 [%0], %1;" \
        :: "r"((uint32_t)(mbar)), "h"((uint16_t)(mask)) : "memory")
#define TCGEN05_FENCE_BEFORE() asm volatile("tcgen05.fence::before_thread_sync;" ::: "memory")
#define TCGEN05_FENCE_AFTER()  asm volatile("tcgen05.fence::after_thread_sync;" ::: "memory")
#define TCGEN05_WAIT_LD()      asm volatile("tcgen05.wait::ld.sync.aligned;" ::: "memory")

#define TCGEN05_LD_32X32B_X32(r, tmem_addr) \
    asm volatile( \
        "tcgen05.ld.sync.aligned.32x32b.x32.b32 " \
        "{%0, %1, %2, %3, %4, %5, %6, %7, " \
        " %8, %9, %10, %11, %12, %13, %14, %15, " \
        " %16, %17, %18, %19, %20, %21, %22, %23, " \
        " %24, %25, %26, %27, %28, %29, %30, %31}, [%32];" \
        : "=r"((r)[0]),  "=r"((r)[1]),  "=r"((r)[2]),  "=r"((r)[3]), \
          "=r"((r)[4]),  "=r"((r)[5]),  "=r"((r)[6]),  "=r"((r)[7]), \
          "=r"((r)[8]),  "=r"((r)[9]),  "=r"((r)[10]), "=r"((r)[11]), \
          "=r"((r)[12]), "=r"((r)[13]), "=r"((r)[14]), "=r"((r)[15]), \
          "=r"((r)[16]), "=r"((r)[17]), "=r"((r)[18]), "=r"((r)[19]), \
          "=r"((r)[20]), "=r"((r)[21]), "=r"((r)[22]), "=r"((r)[23]), \
          "=r"((r)[24]), "=r"((r)[25]), "=r"((r)[26]), "=r"((r)[27]), \
          "=r"((r)[28]), "=r"((r)[29]), "=r"((r)[30]), "=r"((r)[31]) \
        : "r"(tmem_addr))

static constexpr uint64_t SMEM_DESC_BASE_SW128 =
    (uint64_t(2) << 61) | (uint64_t(1) << 46) | (uint64_t(64) << 32) | (uint64_t(1) << 16);
#define MAKE_SMEM_DESC(base_addr) (SMEM_DESC_BASE_SW128 | ((uint64_t)((base_addr) >> 4) & 0x3FFF))

__device__ __forceinline__ void tma_load_2d(uint32_t smem_addr, const void* tm,
                                            int cx, int cy, uint32_t mbar) {
    asm volatile(
        "cp.async.bulk.tensor.2d.shared::cta.global.tile.mbarrier::complete_tx::bytes "
        "[%0], [%1, {%2, %3}], [%4];"
        :: "r"(smem_addr), "l"(tm), "r"(cx), "r"(cy), "r"(mbar) : "memory");
}
__device__ __forceinline__ void tma_load_2d_mc(uint32_t smem_addr, const void* tm,
                                               int cx, int cy, uint32_t mbar, uint16_t mask) {
    asm volatile(
        "cp.async.bulk.tensor.2d.shared::cluster.global.tile.mbarrier::complete_tx::bytes.multicast::cluster "
        "[%0], [%1, {%2, %3}], [%4], %5;"
        :: "r"(smem_addr), "l"(tm), "r"(cx), "r"(cy), "r"(mbar), "h"(mask) : "memory");
}
__device__ __forceinline__ void mma_f16_ss_cg1(uint32_t d_tmem, uint64_t a_desc, uint64_t b_desc,
                                               uint32_t idesc, bool acc) {
    uint32_t en = acc ? 1u : 0u;
    asm volatile(
        "{\n\t.reg .pred p;\n\t"
        "setp.ne.u32 p, %5, 0;\n\t"
        "tcgen05.mma.cta_group::1.kind::f16 [%0], %1, %2, %3, {%4, %4, %4, %4}, p;\n\t"
        "}"
        :: "r"(d_tmem), "l"(a_desc), "l"(b_desc), "r"(idesc), "r"(0u), "r"(en)
        : "memory");
}
#endif  // TC_ON

// ---------------- fused row L2-normalize fp32 -> bf16 ----------------
__global__ __launch_bounds__(256) void normalize_rows_kernel(
    const float* __restrict__ x, const float* __restrict__ p,
    __nv_bfloat16* __restrict__ xn, __nv_bfloat16* __restrict__ pn) {
    int row = blockIdx.x;
    const float* src;
    __nv_bfloat16* dst;
    if (row < Bdim) { src = x + (size_t)row * Ddim; dst = xn + (size_t)row * Ddim; }
    else { src = p + (size_t)(row - Bdim) * Ddim; dst = pn + (size_t)(row - Bdim) * Ddim; }

    const float4* r4 = reinterpret_cast<const float4*>(src);
    __shared__ float red[8];
    float4 v[2];
    float ss = 0.f;
#pragma unroll
    for (int i = 0; i < 2; i++) {
        v[i] = r4[threadIdx.x + i * 256];
        ss = fmaf(v[i].x, v[i].x, ss);
        ss = fmaf(v[i].y, v[i].y, ss);
        ss = fmaf(v[i].z, v[i].z, ss);
        ss = fmaf(v[i].w, v[i].w, ss);
    }
#pragma unroll
    for (int o = 16; o; o >>= 1) ss += __shfl_xor_sync(0xffffffffu, ss, o);
    if ((threadIdx.x & 31) == 0) red[threadIdx.x >> 5] = ss;
    __syncthreads();
    float tot = 0.f;
#pragma unroll
    for (int i = 0; i < 8; i++) tot += red[i];
    float inv = 1.0f / fmaxf(sqrtf(tot), 1e-12f);
    uint2* o2 = reinterpret_cast<uint2*>(dst);
#pragma unroll
    for (int i = 0; i < 2; i++) {
        int c = threadIdx.x + i * 256;
        __nv_bfloat162 lo = __float22bfloat162_rn(make_float2(v[i].x * inv, v[i].y * inv));
        __nv_bfloat162 hi = __float22bfloat162_rn(make_float2(v[i].z * inv, v[i].w * inv));
        uint2 pk;
        pk.x = *reinterpret_cast<uint32_t*>(&lo);
        pk.y = *reinterpret_cast<uint32_t*>(&hi);
        o2[c] = pk;
    }
}

// ---------------- persistent warp-specialized GEMM + epilogue ----------------
__global__ void __launch_bounds__(THREADS, 1) __cluster_dims__(2, 1, 1)
isomax_gemm_kernel(
    const __grid_constant__ CUtensorMap tmA,
    const __grid_constant__ CUtensorMap tmB,
    const __nv_bfloat16* __restrict__ An,
    const __nv_bfloat16* __restrict__ Bn,
    const float* __restrict__ scale_ptr,
    float* __restrict__ out) {
#if TC_ON
    extern __shared__ char smem[];
    uint32_t sb = smem_u32(smem);
    int tid = threadIdx.x, wid = tid >> 5, lid = tid & 31;
    int rank = blockIdx.x & 1;       // cluster rank (cluster dim (2,1,1), contiguous)
    int cid = blockIdx.x >> 1;       // cluster id 0..73

    uint32_t bar_full  = sb + SMEM_BAR_OFF;        // 3 x 8B
    uint32_t bar_empty = sb + SMEM_BAR_OFF + 24;   // 3 x 8B
    uint32_t bar_mdone = sb + SMEM_BAR_OFF + 48;   // 2 x 8B
    uint32_t bar_efree = sb + SMEM_BAR_OFF + 64;   // 2 x 8B
    uint32_t tmem_slot = sb + SMEM_BAR_OFF + 96;

    if (wid == 8) {
        TCGEN05_ALLOC(tmem_slot, 512);
        TCGEN05_RELINQUISH_ALLOC_PERMIT();
    }
    if (tid == 0) {
#pragma unroll
        for (int s = 0; s < STAGES; s++) {
            MBARRIER_INIT(bar_full + s * 8, 1);    // expect_tx arrive from own producer
            MBARRIER_INIT(bar_empty + s * 8, 2);   // commit-multicast from both CTAs' MMA
        }
#pragma unroll
        for (int b = 0; b < 2; b++) {
            MBARRIER_INIT(bar_mdone + b * 8, 1);   // own MMA commit
            MBARRIER_INIT(bar_efree + b * 8, 8);   // ONE arrival per epilogue warp
        }
    }
    __syncthreads();
    CLUSTER_SYNC();   // barriers visible cluster-wide before any multicast

    uint32_t tmem;
    asm volatile("ld.shared.b32 %0, [%1];" : "=r"(tmem) : "r"(tmem_slot));

    if (wid == 9 && elect_one()) {
        // ================= TMA producer =================
        uint32_t cidx = 0;  // global chunk counter
        for (int it = cid; it < TOT_TILES; it += NCLUSTERS) {
            int m_pair = it / NSUP, nq = it % NSUP;
            int my = (2 * m_pair + rank) * BM;
            int ny = nq * BN;
            for (int s = 0; s < KITERS; s++, cidx++) {
                int slot = cidx % STAGES;
                uint32_t use = cidx / STAGES;
                MBARRIER_WAIT_PARITY_RELAXED(bar_empty + slot * 8, (use + 1) & 1);
                MBARRIER_EXPECT_TX(bar_full + slot * 8, STAGE_BYTES);
                uint32_t stg = sb + slot * STAGE_BYTES;
                tma_load_2d(stg, &tmA, s * BK, my, bar_full + slot * 8);
                // cooperative B slice: my half, multicast to both CTAs
                tma_load_2d_mc(stg + STAGE_A + rank * (STAGE_B / 2), &tmB,
                               s * BK, ny + rank * 128, bar_full + slot * 8, 0x3);
            }
        }
    } else if (wid == 8 && elect_one()) {
        // ================= MMA consumer =================
        uint32_t cidx = 0;
        int t = 0;  // local tile counter
        for (int it = cid; it < TOT_TILES; it += NCLUSTERS, t++) {
            int b = t & 1;
            if (t >= 2) {
                MBARRIER_WAIT_PARITY(bar_efree + b * 8, ((t >> 1) - 1) & 1);
                TCGEN05_FENCE_AFTER();
            }
            uint32_t acc0 = tmem + b * 256;
            uint32_t acc1 = acc0 + 128;
            for (int s = 0; s < KITERS; s++, cidx++) {
                int slot = cidx % STAGES;
                uint32_t use = cidx / STAGES;
                MBARRIER_WAIT_PARITY(bar_full + slot * 8, use & 1);
                uint32_t stg = sb + slot * STAGE_BYTES;
                uint64_t ad  = MAKE_SMEM_DESC(stg);
                uint64_t bd0 = MAKE_SMEM_DESC(stg + STAGE_A);
                uint64_t bd1 = MAKE_SMEM_DESC(stg + STAGE_A + STAGE_B / 2);
#pragma unroll
                for (int k = 0; k < BK / 16; k++) {
                    bool acc = (s | k) != 0;
                    mma_f16_ss_cg1(acc0, ad + k * 2, bd0 + k * 2, MMA_IDESC, acc);
                    mma_f16_ss_cg1(acc1, ad + k * 2, bd1 + k * 2, MMA_IDESC, acc);
                }
                TCGEN05_COMMIT_MC(bar_empty + slot * 8, 0x3);
            }
            TCGEN05_COMMIT(bar_mdone + b * 8);
        }
    } else if (wid < 8) {
        // ================= epilogue (8 warps, 256 threads) =================
        float sgn = fabsf(scale_ptr[0]);
        float* tile = reinterpret_cast<float*>(smem + SMEM_TRANS_OFF);
        int sub = wid & 3, chalf = wid >> 2;
        int t = 0;
        for (int it = cid; it < TOT_TILES; it += NCLUSTERS, t++) {
            int b = t & 1;
            int m_pair = it / NSUP, nq = it % NSUP;
            int gm0 = (2 * m_pair + rank) * BM;
            int gn0 = nq * BN;
            MBARRIER_WAIT_PARITY(bar_mdone + b * 8, (t >> 1) & 1);
            TCGEN05_FENCE_AFTER();
#pragma unroll
            for (int h = 0; h < 2; h++) {
                uint32_t regs[64];
                uint32_t base = tmem + b * 256 + h * 128 + chalf * 64;
                TCGEN05_LD_32X32B_X32(regs, base);
                TCGEN05_LD_32X32B_X32(regs + 32, base + 32);
                TCGEN05_WAIT_LD();
                int row = sub * 32 + lid;
#pragma unroll
                for (int c = 0; c < 64; c++) {
                    float v = __uint_as_float(regs[c]);
                    float d2 = fmaxf(2.0f - 2.0f * v, 0.0f);
                    tile[row * 129 + chalf * 64 + c] = -sgn * sqrtf(d2);
                }
                asm volatile("bar.sync 1, 256;" ::: "memory");
#pragma unroll 8
                for (int i2 = 0; i2 < 64; i2++) {
                    int idx = i2 * 256 + tid;
                    int m = idx >> 7, n = idx & 127;
                    int gn = gn0 + h * 128 + n;
                    if (gn < Mdim)
                        out[(size_t)(gm0 + m) * Mdim + gn] = tile[m * 129 + n];
                }
                asm volatile("bar.sync 1, 256;" ::: "memory");
            }
            TCGEN05_FENCE_BEFORE();
            if (lid == 0) MBARRIER_ARRIVE(bar_efree + b * 8);   // 1 arrival/warp (count=8)
        }
    }

    __syncthreads();
    CLUSTER_SYNC();   // no CTA exits while partner multicasts may be in flight
    if (wid == 8) TCGEN05_DEALLOC(tmem, 512);
#else
    // =================== SIMT fallback (non-'a' pass only) ===================
    extern __shared__ char smem[];
    constexpr int LDT = 72;
    __nv_bfloat16* sA = reinterpret_cast<__nv_bfloat16*>(smem);   // 128 x LDT
    __nv_bfloat16* sB = sA + 128 * LDT;                            // 128 x LDT

    int tid = threadIdx.x;
    int rank = blockIdx.x & 1;
    int cid = blockIdx.x >> 1;
    float sgn = fabsf(scale_ptr[0]);

    for (int it = cid; it < TOT_TILES; it += NCLUSTERS) {
        int m_pair = it / NSUP, nq = it % NSUP;
        int gm0 = (2 * m_pair + rank) * BM;
        for (int h = 0; h < 2; h++) {
            int gn0 = nq * BN + h * 128;
            float acc[8][8];
#pragma unroll
            for (int i = 0; i < 8; i++)
#pragma unroll
                for (int j = 0; j < 8; j++) acc[i][j] = 0.f;
            int tx = tid & 15, ty = (tid >> 4) & 15;
            for (int s = 0; s < KITERS; s++) {
                int k0 = s * BK;
                if (tid < 256) {
#pragma unroll
                    for (int i = 0; i < 4; i++) {
                        int v = tid + 256 * i;
                        int r = v >> 3, c8 = (v & 7) * 8;
                        *reinterpret_cast<uint4*>(sA + r * LDT + c8) =
                            *reinterpret_cast<const uint4*>(An + (size_t)(gm0 + r) * Ddim + k0 + c8);
                        int br = gn0 + r; if (br >= Mdim) br = Mdim - 1;
                        *reinterpret_cast<uint4*>(sB + r * LDT + c8) =
                            *reinterpret_cast<const uint4*>(Bn + (size_t)br * Ddim + k0 + c8);
                    }
                }
                __syncthreads();
                if (tid < 256) {
#pragma unroll 8
                    for (int kk = 0; kk < BK; kk++) {
                        float ar[8], br[8];
#pragma unroll
                        for (int i = 0; i < 8; i++) ar[i] = __bfloat162float(sA[(ty * 8 + i) * LDT + kk]);
#pragma unroll
                        for (int j = 0; j < 8; j++) br[j] = __bfloat162float(sB[(tx * 8 + j) * LDT + kk]);
#pragma unroll
                        for (int i = 0; i < 8; i++)
#pragma unroll
                            for (int j = 0; j < 8; j++) acc[i][j] = fmaf(ar[i], br[j], acc[i][j]);
                    }
                }
                __syncthreads();
            }
            if (tid < 256) {
#pragma unroll
                for (int i = 0; i < 8; i++) {
                    int gm = gm0 + ty * 8 + i;
#pragma unroll
                    for (int j = 0; j < 8; j++) {
                        int gn = gn0 + tx * 8 + j;
                        if (gn < Mdim) {
                            float d2 = fmaxf(2.0f - 2.0f * acc[i][j], 0.0f);
                            out[(size_t)gm * Mdim + gn] = -sgn * sqrtf(d2);
                        }
                    }
                }
            }
        }
    }
#endif
}

// ---------------- host launch ----------------
typedef CUresult (*PFN_tmEncode)(
    CUtensorMap*, CUtensorMapDataType, cuuint32_t, void*,
    const cuuint64_t*, const cuuint64_t*, const cuuint32_t*, const cuuint32_t*,
    CUtensorMapInterleave, CUtensorMapSwizzle, CUtensorMapL2promotion, CUtensorMapFloatOOBfill);

extern "C" void kernel_launch(void* const* d_in, const int* in_sizes, int n_in,
                              void* d_out, int out_size) {
    const float* x      = (const float*)d_in[0];
    const float* protos = (const float*)d_in[1];
    const float* dscale = (const float*)d_in[2];
    float* out = (float*)d_out;

    void *pA = nullptr, *pB = nullptr;
    cudaGetSymbolAddress(&pA, g_xn);
    cudaGetSymbolAddress(&pB, g_pn);

    normalize_rows_kernel<<<Bdim + Mdim, 256>>>(x, protos, (__nv_bfloat16*)pA, (__nv_bfloat16*)pB);

    void* fp = nullptr;
    cudaDriverEntryPointQueryResult qr;
    cudaGetDriverEntryPoint("cuTensorMapEncodeTiled", &fp, cudaEnableDefault, &qr);
    PFN_tmEncode enc = (PFN_tmEncode)fp;

    CUtensorMap tmA{}, tmB{};
    {
        cuuint64_t dims[2]    = {(cuuint64_t)Ddim, (cuuint64_t)Bdim};
        cuuint64_t strides[1] = {(cuuint64_t)Ddim * sizeof(__nv_bfloat16)};
        cuuint32_t box[2]     = {(cuuint32_t)BK, (cuuint32_t)BM};
        cuuint32_t es[2]      = {1, 1};
        enc(&tmA, CU_TENSOR_MAP_DATA_TYPE_BFLOAT16, 2, pA, dims, strides, box, es,
            CU_TENSOR_MAP_INTERLEAVE_NONE, CU_TENSOR_MAP_SWIZZLE_128B,
            CU_TENSOR_MAP_L2_PROMOTION_L2_128B, CU_TENSOR_MAP_FLOAT_OOB_FILL_NONE);
    }
    {
        cuuint64_t dims[2]    = {(cuuint64_t)Ddim, (cuuint64_t)Mdim};
        cuuint64_t strides[1] = {(cuuint64_t)Ddim * sizeof(__nv_bfloat16)};
        cuuint32_t box[2]     = {(cuuint32_t)BK, 128};   // one 128-row multicast slice
        cuuint32_t es[2]      = {1, 1};
        enc(&tmB, CU_TENSOR_MAP_DATA_TYPE_BFLOAT16, 2, pB, dims, strides, box, es,
            CU_TENSOR_MAP_INTERLEAVE_NONE, CU_TENSOR_MAP_SWIZZLE_128B,
            CU_TENSOR_MAP_L2_PROMOTION_L2_128B, CU_TENSOR_MAP_FLOAT_OOB_FILL_NONE);
    }

    cudaFuncSetAttribute(isomax_gemm_kernel,
                         cudaFuncAttributeMaxDynamicSharedMemorySize, SMEM_TOTAL);
    isomax_gemm_kernel<<<2 * NCLUSTERS, THREADS, SMEM_TOTAL>>>(
        tmA, tmB, (const __nv_bfloat16*)pA, (const __nv_bfloat16*)pB, dscale, out);
}

// round 7
// speedup vs baseline: 1.5877x; 1.2041x over previous
#include <cuda_runtime.h>
#include <cuda.h>
#include <cuda_bf16.h>
#include <cstdint>

// tcgen05 / cg2-TMA only in the arch-specific pass; plain sm_103 pass gets a
// correct SIMT fallback.
#if !defined(__CUDA_ARCH__)
#  define TC_ON 1
#elif defined(__CUDA_ARCH_FEAT_SM103_ALL) || defined(__CUDA_ARCH_FEAT_SM100_ALL) || defined(__CUDA_ARCH_FEAT_SM101_ALL)
#  define TC_ON 1
#else
#  define TC_ON 0
#endif

// Problem dims
static constexpr int Bdim = 4096;
static constexpr int Mdim = 12893;
static constexpr int Ddim = 2048;

// cg2 tiling: cluster of 2 CTAs computes a 256(m) x 256(n) tile with ONE
// M=256/N=256 tcgen05 cg2 MMA chain. Each CTA holds 128 A-rows + 128 B-rows
// (its N-half) per stage -> 32KB/stage/SM, half of the R6 feed rate.
static constexpr int BM = 128;        // per-CTA A rows (M_atom = 256 across pair)
static constexpr int BN = 256;        // full N per cluster tile (128 per CTA SMEM)
static constexpr int BK = 64;
static constexpr int STAGES = 4;
static constexpr int KITERS = Ddim / BK;             // 32
static constexpr int STAGE_A = BM * 128;             // 16384
static constexpr int STAGE_B = 128 * 128;            // 16384 (N-half)
static constexpr int STAGE_BYTES = STAGE_A + STAGE_B;    // 32768
static constexpr int SMEM_BAR_OFF = STAGES * STAGE_BYTES; // 131072
//   full[4]@+0, empty[4]@+32, mdone[2]@+64, efree[2]@+80, tmemptr@+96
static constexpr int SMEM_TRANS_OFF = SMEM_BAR_OFF + 128;     // 131200
static constexpr int SMEM_TOTAL = SMEM_TRANS_OFF + 128 * 129 * 4;  // 197248

// Tile grid
static constexpr int NSUP = (Mdim + BN - 1) / BN;    // 51
static constexpr int MSUP = Bdim / 256;              // 16 (256 m per cluster tile)
static constexpr int TOT_TILES = NSUP * MSUP;        // 816
static constexpr int NCLUSTERS = 74;

static constexpr int THREADS = 320;                  // w0-7 epi, w8 mma, w9 tma

// idesc kind::f16 bf16/bf16 fp32-acc, M=256 (cg2), N=256
static constexpr uint32_t MMA_IDESC =
    (1u << 4) | (1u << 7) | (1u << 10) | ((256 / 8) << 17) | ((256 / 16) << 24);

__device__ __nv_bfloat16 g_xn[(size_t)Bdim * Ddim];
__device__ __nv_bfloat16 g_pn[(size_t)Mdim * Ddim];

// ---------------- portable PTX helpers ----------------
__device__ __forceinline__ uint32_t smem_u32(const void* p) {
    uint32_t a;
    asm("{ .reg .u64 t; cvta.to.shared.u64 t, %1; cvt.u32.u64 %0, t; }" : "=r"(a) : "l"(p));
    return a;
}
__device__ __forceinline__ uint32_t elect_one() {
    uint32_t p;
    asm volatile("{\n\t.reg .pred p;\n\telect.sync _|p, 0xFFFFFFFF;\n\tselp.b32 %0, 1, 0, p;\n\t}" : "=r"(p));
    return p;
}
__device__ __forceinline__ uint32_t cluster_rank() {
    uint32_t r;
    asm("mov.u32 %0, %%cluster_ctarank;" : "=r"(r));
    return r;
}

#define MBARRIER_INIT(addr, count) \
    asm volatile("mbarrier.init.shared.b64 [%0], %1;" :: "r"((uint32_t)(addr)), "r"((uint32_t)(count)) : "memory")
#define MBARRIER_EXPECT_TX(addr, bytes) \
    asm volatile("mbarrier.arrive.expect_tx.shared.b64 _, [%0], %1;" :: "r"((uint32_t)(addr)), "r"((uint32_t)(bytes)) : "memory")
#define MBARRIER_ARRIVE_CLUSTER(local_mbar_addr, target_rank) \
    asm volatile( \
        "{\n\t.reg .b32 remAddr32;\n\t" \
        "mapa.shared::cluster.u32 remAddr32, %0, %1;\n\t" \
        "mbarrier.arrive.shared::cluster.b64 _, [remAddr32];\n\t}" \
        :: "r"((uint32_t)(local_mbar_addr)), "r"((uint32_t)(target_rank)) : "memory")

#define MBARRIER_WAIT_PARITY(mbar_smem_addr, phase_parity) do { \
    uint32_t _mbar = (uint32_t)(mbar_smem_addr); \
    uint32_t _parity = (uint32_t)(phase_parity); \
    uint32_t _done; \
    asm volatile( \
        "{\n\t.reg .pred p;\n\t" \
        "mbarrier.try_wait.parity.acquire.cta.shared::cta.b64 p, [%1], %2;\n\t" \
        "selp.b32 %0, 1, 0, p;\n\t}" \
        : "=r"(_done) : "r"(_mbar), "r"(_parity) : "memory"); \
    if (!_done) { \
        asm volatile( \
            "{\n\t.reg .pred P1;\n\t" \
            "WAIT_LOOP_%=:\n\t" \
            "mbarrier.try_wait.parity.acquire.cta.shared::cta.b64 P1, [%0], %1, 0x989680;\n\t" \
            "@P1 bra.uni WAIT_DONE_%=;\n\t" \
            "bra.uni WAIT_LOOP_%=;\n\t" \
            "WAIT_DONE_%=:\n\t}" \
            :: "r"(_mbar), "r"(_parity) : "memory"); \
    } \
} while(0)

#define MBARRIER_WAIT_PARITY_RELAXED(mbar_smem_addr, phase_parity) do { \
    uint32_t _mbar = (uint32_t)(mbar_smem_addr); \
    uint32_t _parity = (uint32_t)(phase_parity); \
    uint32_t _done; \
    asm volatile( \
        "{\n\t.reg .pred p;\n\t" \
        "mbarrier.try_wait.parity.relaxed.cta.shared::cta.b64 p, [%1], %2, 0x989680;\n\t" \
        "selp.b32 %0, 1, 0, p;\n\t}" \
        : "=r"(_done) : "r"(_mbar), "r"(_parity) : "memory"); \
    if (!_done) { \
        asm volatile( \
            "{\n\t.reg .pred P1;\n\t" \
            "WAIT_LOOP_%=:\n\t" \
            "mbarrier.try_wait.parity.relaxed.cta.shared::cta.b64 P1, [%0], %1, 0x989680;\n\t" \
            "@P1 bra.uni WAIT_DONE_%=;\n\t" \
            "bra.uni WAIT_LOOP_%=;\n\t" \
            "WAIT_DONE_%=:\n\t}" \
            :: "r"(_mbar), "r"(_parity) : "memory"); \
    } \
} while(0)

#define CLUSTER_SYNC() do { \
    asm volatile("barrier.cluster.arrive.aligned;" ::: "memory"); \
    asm volatile("barrier.cluster.wait.aligned;" ::: "memory"); \
} while(0)

// ---------------- tcgen05 / cg2 helpers (arch-specific pass) ----------------
#if TC_ON
#define TCGEN05_ALLOC_CG2(smem_result_addr, nCols) \
    asm volatile("tcgen05.alloc.cta_group::2.sync.aligned.shared::cta.b32 [%0], %1;" \
        :: "r"((uint32_t)(smem_result_addr)), "r"((uint32_t)(nCols)) : "memory")
#define TCGEN05_DEALLOC_CG2(tmem_addr, nCols) \
    asm volatile("tcgen05.dealloc.cta_group::2.sync.aligned.b32 %0, %1;" :: "r"(tmem_addr), "r"((uint32_t)(nCols)))
#define TCGEN05_RELINQUISH_CG2() \
    asm volatile("tcgen05.relinquish_alloc_permit.cta_group::2.sync.aligned;")
#define TCGEN05_COMMIT_MC_CG2(mbar, mask) \
    asm volatile("tcgen05.commit.cta_group::2.mbarrier::arrive::one.shared::cluster.multicast::cluster.b64 [%0], %1;" \
        :: "r"((uint32_t)(mbar)), "h"((uint16_t)(mask)) : "memory")
#define TCGEN05_FENCE_BEFORE() asm volatile("tcgen05.fence::before_thread_sync;" ::: "memory")
#define TCGEN05_FENCE_AFTER()  asm volatile("tcgen05.fence::after_thread_sync;" ::: "memory")
#define TCGEN05_WAIT_LD()      asm volatile("tcgen05.wait::ld.sync.aligned;" ::: "memory")

#define TCGEN05_LD_32X32B_X32(r, tmem_addr) \
    asm volatile( \
        "tcgen05.ld.sync.aligned.32x32b.x32.b32 " \
        "{%0, %1, %2, %3, %4, %5, %6, %7, " \
        " %8, %9, %10, %11, %12, %13, %14, %15, " \
        " %16, %17, %18, %19, %20, %21, %22, %23, " \
        " %24, %25, %26, %27, %28, %29, %30, %31}, [%32];" \
        : "=r"((r)[0]),  "=r"((r)[1]),  "=r"((r)[2]),  "=r"((r)[3]), \
          "=r"((r)[4]),  "=r"((r)[5]),  "=r"((r)[6]),  "=r"((r)[7]), \
          "=r"((r)[8]),  "=r"((r)[9]),  "=r"((r)[10]), "=r"((r)[11]), \
          "=r"((r)[12]), "=r"((r)[13]), "=r"((r)[14]), "=r"((r)[15]), \
          "=r"((r)[16]), "=r"((r)[17]), "=r"((r)[18]), "=r"((r)[19]), \
          "=r"((r)[20]), "=r"((r)[21]), "=r"((r)[22]), "=r"((r)[23]), \
          "=r"((r)[24]), "=r"((r)[25]), "=r"((r)[26]), "=r"((r)[27]), \
          "=r"((r)[28]), "=r"((r)[29]), "=r"((r)[30]), "=r"((r)[31]) \
        : "r"(tmem_addr))

static constexpr uint64_t SMEM_DESC_BASE_SW128 =
    (uint64_t(2) << 61) | (uint64_t(1) << 46) | (uint64_t(64) << 32) | (uint64_t(1) << 16);
#define MAKE_SMEM_DESC(base_addr) (SMEM_DESC_BASE_SW128 | ((uint64_t)((base_addr) >> 4) & 0x3FFF))

// cg2 TMA 3D load: both CTAs execute; complete_tx routes to leader CTA's
// barrier (bit 24 cleared), aggregating tx across the pair.
__device__ __forceinline__ void tma_load_3d_cg2(uint32_t smem_addr, const void* tm,
                                                int cx, int cy, uint32_t mbar) {
    asm volatile(
        "{\n\t.reg .b32 lb;\n\t"
        "and.b32 lb, %5, 0xFEFFFFFF;\n\t"
        "cp.async.bulk.tensor.3d.cta_group::2.shared::cluster.global"
        ".tile.mbarrier::complete_tx::bytes [%0], [%1, {%2, %3, %4}], [lb];\n\t}"
        :: "r"(smem_addr), "l"(tm), "r"(cx), "r"(cy), "r"(0), "r"(mbar) : "memory");
}

// cg2 SS bf16 MMA, fp32 accum, M=256 across the pair, B split N/2 per CTA
__device__ __forceinline__ void mma_f16_ss_cg2(uint32_t d_tmem, uint64_t a_desc, uint64_t b_desc,
                                               uint32_t idesc, bool acc) {
    uint32_t en = acc ? 1u : 0u;
    asm volatile(
        "{\n\t.reg .pred p;\n\t"
        "setp.ne.u32 p, %6, 0;\n\t"
        "tcgen05.mma.cta_group::2.kind::f16 [%0], %1, %2, %3, "
        "{%4, %4, %4, %4, %4, %4, %4, %4}, p;\n\t}"
        :: "r"(d_tmem), "l"(a_desc), "l"(b_desc), "r"(idesc),
           "r"(0u), "r"(0u), "r"(en)
        : "memory");
}
#endif  // TC_ON

// ---------------- fused row L2-normalize fp32 -> bf16 (2 rows/block) ----------------
__global__ __launch_bounds__(256) void normalize_rows_kernel(
    const float* __restrict__ x, const float* __restrict__ p,
    __nv_bfloat16* __restrict__ xn, __nv_bfloat16* __restrict__ pn) {
    int nrows = Bdim + Mdim;
    int r0 = blockIdx.x * 2;
    __shared__ float red[2][8];
#pragma unroll
    for (int rr = 0; rr < 2; rr++) {
        int row = r0 + rr;
        if (row >= nrows) break;
        const float* src;
        __nv_bfloat16* dst;
        if (row < Bdim) { src = x + (size_t)row * Ddim; dst = xn + (size_t)row * Ddim; }
        else { src = p + (size_t)(row - Bdim) * Ddim; dst = pn + (size_t)(row - Bdim) * Ddim; }
        const float4* r4 = reinterpret_cast<const float4*>(src);
        float4 v[2];
        float ss = 0.f;
#pragma unroll
        for (int i = 0; i < 2; i++) {
            v[i] = r4[threadIdx.x + i * 256];
            ss = fmaf(v[i].x, v[i].x, ss);
            ss = fmaf(v[i].y, v[i].y, ss);
            ss = fmaf(v[i].z, v[i].z, ss);
            ss = fmaf(v[i].w, v[i].w, ss);
        }
#pragma unroll
        for (int o = 16; o; o >>= 1) ss += __shfl_xor_sync(0xffffffffu, ss, o);
        if ((threadIdx.x & 31) == 0) red[rr][threadIdx.x >> 5] = ss;
        __syncthreads();
        float tot = 0.f;
#pragma unroll
        for (int i = 0; i < 8; i++) tot += red[rr][i];
        float inv = 1.0f / fmaxf(sqrtf(tot), 1e-12f);
        uint2* o2 = reinterpret_cast<uint2*>(dst);
#pragma unroll
        for (int i = 0; i < 2; i++) {
            int c = threadIdx.x + i * 256;
            __nv_bfloat162 lo = __float22bfloat162_rn(make_float2(v[i].x * inv, v[i].y * inv));
            __nv_bfloat162 hi = __float22bfloat162_rn(make_float2(v[i].z * inv, v[i].w * inv));
            uint2 pk;
            pk.x = *reinterpret_cast<uint32_t*>(&lo);
            pk.y = *reinterpret_cast<uint32_t*>(&hi);
            o2[c] = pk;
        }
        __syncthreads();
    }
}

// ---------------- persistent cg2 warp-specialized GEMM + epilogue ----------------
__global__ void __launch_bounds__(THREADS, 1) __cluster_dims__(2, 1, 1)
isomax_gemm_kernel(
    const __grid_constant__ CUtensorMap tmA,
    const __grid_constant__ CUtensorMap tmB,
    const __nv_bfloat16* __restrict__ An,
    const __nv_bfloat16* __restrict__ Bn,
    const float* __restrict__ scale_ptr,
    float* __restrict__ out) {
#if TC_ON
    extern __shared__ char smem[];
    uint32_t sb = smem_u32(smem);
    int tid = threadIdx.x, wid = tid >> 5, lid = tid & 31;
    uint32_t rank = cluster_rank();
    int cid = blockIdx.x >> 1;       // cluster id 0..73

    uint32_t bar_full  = sb + SMEM_BAR_OFF;        // 4 x 8B (leader-resident semantics)
    uint32_t bar_empty = sb + SMEM_BAR_OFF + 32;   // 4 x 8B (per CTA)
    uint32_t bar_mdone = sb + SMEM_BAR_OFF + 64;   // 2 x 8B (per CTA)
    uint32_t bar_efree = sb + SMEM_BAR_OFF + 80;   // 2 x 8B (leader, count=2)
    uint32_t tmem_slot = sb + SMEM_BAR_OFF + 96;

    if (wid == 8) {
        TCGEN05_ALLOC_CG2(tmem_slot, 512);
        TCGEN05_RELINQUISH_CG2();
    }
    if (tid == 0) {
#pragma unroll
        for (int s = 0; s < STAGES; s++) {
            MBARRIER_INIT(bar_full + s * 8, 1);    // leader: expect_tx arrive (1) + tx from 4 loads
            MBARRIER_INIT(bar_empty + s * 8, 1);   // cg2 commit-multicast, 1 arrive per CTA
        }
#pragma unroll
        for (int b = 0; b < 2; b++) {
            MBARRIER_INIT(bar_mdone + b * 8, 1);   // cg2 commit-multicast
            MBARRIER_INIT(bar_efree + b * 8, 2);   // one cluster-arrive per CTA's epilogue
        }
    }
    __syncthreads();
    CLUSTER_SYNC();   // all barriers visible cluster-wide before cg2 TMA / commits

    uint32_t tmem;
    asm volatile("ld.shared.b32 %0, [%1];" : "=r"(tmem) : "r"(tmem_slot));

    if (wid == 9 && elect_one()) {
        // ================= TMA producer (both CTAs) =================
        uint32_t cidx = 0;
        for (int it = cid; it < TOT_TILES; it += NCLUSTERS) {
            int m_sup = it / NSUP, nq = it % NSUP;
            int my = m_sup * 256 + (int)rank * BM;          // own 128 A rows
            int ny = nq * BN + (int)rank * 128;             // own 128 B rows (N-half)
            for (int s = 0; s < KITERS; s++, cidx++) {
                int slot = cidx & (STAGES - 1);
                uint32_t use = cidx / STAGES;
                MBARRIER_WAIT_PARITY_RELAXED(bar_empty + slot * 8, (use + 1) & 1);
                if (rank == 0)
                    MBARRIER_EXPECT_TX(bar_full + slot * 8, 2 * STAGE_BYTES);  // both CTAs' bytes
                uint32_t stg = sb + slot * STAGE_BYTES;
                tma_load_3d_cg2(stg, &tmA, s * BK, my, bar_full + slot * 8);
                tma_load_3d_cg2(stg + STAGE_A, &tmB, s * BK, ny, bar_full + slot * 8);
            }
        }
    } else if (wid == 8 && rank == 0 && elect_one()) {
        // ================= MMA (leader CTA only) =================
        uint32_t cidx = 0;
        int t = 0;
        for (int it = cid; it < TOT_TILES; it += NCLUSTERS, t++) {
            int b = t & 1;
            if (t >= 2) {
                MBARRIER_WAIT_PARITY(bar_efree + b * 8, ((t >> 1) - 1) & 1);
                TCGEN05_FENCE_AFTER();
            }
            uint32_t acc = tmem + b * 256;
            for (int s = 0; s < KITERS; s++, cidx++) {
                int slot = cidx & (STAGES - 1);
                uint32_t use = cidx / STAGES;
                MBARRIER_WAIT_PARITY(bar_full + slot * 8, use & 1);
                uint32_t stg = sb + slot * STAGE_BYTES;
                uint64_t ad = MAKE_SMEM_DESC(stg);
                uint64_t bd = MAKE_SMEM_DESC(stg + STAGE_A);
#pragma unroll
                for (int k = 0; k < BK / 16; k++)
                    mma_f16_ss_cg2(acc, ad + k * 2, bd + k * 2, MMA_IDESC, (s | k) != 0);
                TCGEN05_COMMIT_MC_CG2(bar_empty + slot * 8, 0x3);
            }
            TCGEN05_COMMIT_MC_CG2(bar_mdone + b * 8, 0x3);
        }
    } else if (wid < 8) {
        // ================= epilogue (8 warps, 256 threads, both CTAs) =================
        float sgn = fabsf(scale_ptr[0]);
        float* tile = reinterpret_cast<float*>(smem + SMEM_TRANS_OFF);
        int sub = wid & 3, chalf = wid >> 2;
        int t = 0;
        for (int it = cid; it < TOT_TILES; it += NCLUSTERS, t++) {
            int b = t & 1;
            int m_sup = it / NSUP, nq = it % NSUP;
            int gm0 = m_sup * 256 + (int)rank * BM;   // this CTA's TMEM rows
            int gn0 = nq * BN;
            MBARRIER_WAIT_PARITY(bar_mdone + b * 8, (t >> 1) & 1);
            TCGEN05_FENCE_AFTER();
#pragma unroll
            for (int h = 0; h < 2; h++) {
                uint32_t regs[64];
                uint32_t base = tmem + b * 256 + h * 128 + chalf * 64;
                TCGEN05_LD_32X32B_X32(regs, base);
                TCGEN05_LD_32X32B_X32(regs + 32, base + 32);
                TCGEN05_WAIT_LD();
                int row = sub * 32 + lid;
#pragma unroll
                for (int c = 0; c < 64; c++) {
                    float v = __uint_as_float(regs[c]);
                    float d2 = fmaxf(2.0f - 2.0f * v, 0.0f);
                    tile[row * 129 + chalf * 64 + c] = -sgn * sqrtf(d2);
                }
                asm volatile("bar.sync 1, 256;" ::: "memory");
#pragma unroll 8
                for (int i2 = 0; i2 < 64; i2++) {
                    int idx = i2 * 256 + tid;
                    int m = idx >> 7, n = idx & 127;
                    int gn = gn0 + h * 128 + n;
                    if (gn < Mdim)
                        out[(size_t)(gm0 + m) * Mdim + gn] = tile[m * 129 + n];
                }
                asm volatile("bar.sync 1, 256;" ::: "memory");
            }
            TCGEN05_FENCE_BEFORE();
            if (wid == 0 && elect_one())
                MBARRIER_ARRIVE_CLUSTER(bar_efree + b * 8, 0);   // both CTAs -> leader (count=2)
        }
    }

    __syncthreads();
    CLUSTER_SYNC();   // no CTA exits while peer cg2 traffic may be in flight
    if (wid == 8) TCGEN05_DEALLOC_CG2(tmem, 512);
#else
    // =================== SIMT fallback (non-'a' pass only) ===================
    extern __shared__ char smem[];
    constexpr int LDT = 72;
    __nv_bfloat16* sA = reinterpret_cast<__nv_bfloat16*>(smem);
    __nv_bfloat16* sB = sA + 128 * LDT;

    int tid = threadIdx.x;
    int rank = blockIdx.x & 1;
    int cid = blockIdx.x >> 1;
    float sgn = fabsf(scale_ptr[0]);

    for (int it = cid; it < TOT_TILES; it += NCLUSTERS) {
        int m_sup = it / NSUP, nq = it % NSUP;
        int gm0 = m_sup * 256 + rank * BM;
        for (int h = 0; h < 2; h++) {
            int gn0 = nq * BN + h * 128;
            float acc[8][8];
#pragma unroll
            for (int i = 0; i < 8; i++)
#pragma unroll
                for (int j = 0; j < 8; j++) acc[i][j] = 0.f;
            int tx = tid & 15, ty = (tid >> 4) & 15;
            for (int s = 0; s < KITERS; s++) {
                int k0 = s * BK;
                if (tid < 256) {
#pragma unroll
                    for (int i = 0; i < 4; i++) {
                        int v = tid + 256 * i;
                        int r = v >> 3, c8 = (v & 7) * 8;
                        *reinterpret_cast<uint4*>(sA + r * LDT + c8) =
                            *reinterpret_cast<const uint4*>(An + (size_t)(gm0 + r) * Ddim + k0 + c8);
                        int br = gn0 + r; if (br >= Mdim) br = Mdim - 1;
                        *reinterpret_cast<uint4*>(sB + r * LDT + c8) =
                            *reinterpret_cast<const uint4*>(Bn + (size_t)br * Ddim + k0 + c8);
                    }
                }
                __syncthreads();
                if (tid < 256) {
#pragma unroll 8
                    for (int kk = 0; kk < BK; kk++) {
                        float ar[8], br[8];
#pragma unroll
                        for (int i = 0; i < 8; i++) ar[i] = __bfloat162float(sA[(ty * 8 + i) * LDT + kk]);
#pragma unroll
                        for (int j = 0; j < 8; j++) br[j] = __bfloat162float(sB[(tx * 8 + j) * LDT + kk]);
#pragma unroll
                        for (int i = 0; i < 8; i++)
#pragma unroll
                            for (int j = 0; j < 8; j++) acc[i][j] = fmaf(ar[i], br[j], acc[i][j]);
                    }
                }
                __syncthreads();
            }
            if (tid < 256) {
#pragma unroll
                for (int i = 0; i < 8; i++) {
                    int gm = gm0 + ty * 8 + i;
#pragma unroll
                    for (int j = 0; j < 8; j++) {
                        int gn = gn0 + tx * 8 + j;
                        if (gn < Mdim) {
                            float d2 = fmaxf(2.0f - 2.0f * acc[i][j], 0.0f);
                            out[(size_t)gm * Mdim + gn] = -sgn * sqrtf(d2);
                        }
                    }
                }
            }
        }
    }
#endif
}

// ---------------- host launch ----------------
typedef CUresult (*PFN_tmEncode)(
    CUtensorMap*, CUtensorMapDataType, cuuint32_t, void*,
    const cuuint64_t*, const cuuint64_t*, const cuuint32_t*, const cuuint32_t*,
    CUtensorMapInterleave, CUtensorMapSwizzle, CUtensorMapL2promotion, CUtensorMapFloatOOBfill);

extern "C" void kernel_launch(void* const* d_in, const int* in_sizes, int n_in,
                              void* d_out, int out_size) {
    const float* x      = (const float*)d_in[0];
    const float* protos = (const float*)d_in[1];
    const float* dscale = (const float*)d_in[2];
    float* out = (float*)d_out;

    void *pA = nullptr, *pB = nullptr;
    cudaGetSymbolAddress(&pA, g_xn);
    cudaGetSymbolAddress(&pB, g_pn);

    int nrows = Bdim + Mdim;
    normalize_rows_kernel<<<(nrows + 1) / 2, 256>>>(x, protos, (__nv_bfloat16*)pA, (__nv_bfloat16*)pB);

    void* fp = nullptr;
    cudaDriverEntryPointQueryResult qr;
    cudaGetDriverEntryPoint("cuTensorMapEncodeTiled", &fp, cudaEnableDefault, &qr);
    PFN_tmEncode enc = (PFN_tmEncode)fp;

    CUtensorMap tmA{}, tmB{};
    {
        cuuint64_t dims[3]    = {(cuuint64_t)Ddim, (cuuint64_t)Bdim, 1};
        cuuint64_t strides[2] = {(cuuint64_t)Ddim * sizeof(__nv_bfloat16),
                                 (cuuint64_t)Bdim * Ddim * sizeof(__nv_bfloat16)};
        cuuint32_t box[3]     = {(cuuint32_t)BK, (cuuint32_t)BM, 1};
        cuuint32_t es[3]      = {1, 1, 1};
        enc(&tmA, CU_TENSOR_MAP_DATA_TYPE_BFLOAT16, 3, pA, dims, strides, box, es,
            CU_TENSOR_MAP_INTERLEAVE_NONE, CU_TENSOR_MAP_SWIZZLE_128B,
            CU_TENSOR_MAP_L2_PROMOTION_L2_128B, CU_TENSOR_MAP_FLOAT_OOB_FILL_NONE);
    }
    {
        cuuint64_t dims[3]    = {(cuuint64_t)Ddim, (cuuint64_t)Mdim, 1};
        cuuint64_t strides[2] = {(cuuint64_t)Ddim * sizeof(__nv_bfloat16),
                                 (cuuint64_t)Mdim * Ddim * sizeof(__nv_bfloat16)};
        cuuint32_t box[3]     = {(cuuint32_t)BK, 128, 1};   // N-half per CTA
        cuuint32_t es[3]      = {1, 1, 1};
        enc(&tmB, CU_TENSOR_MAP_DATA_TYPE_BFLOAT16, 3, pB, dims, strides, box, es,
            CU_TENSOR_MAP_INTERLEAVE_NONE, CU_TENSOR_MAP_SWIZZLE_128B,
            CU_TENSOR_MAP_L2_PROMOTION_L2_128B, CU_TENSOR_MAP_FLOAT_OOB_FILL_NONE);
    }

    cudaFuncSetAttribute(isomax_gemm_kernel,
                         cudaFuncAttributeMaxDynamicSharedMemorySize, SMEM_TOTAL);
    isomax_gemm_kernel<<<2 * NCLUSTERS, THREADS, SMEM_TOTAL>>>(
        tmA, tmB, (const __nv_bfloat16*)pA, (const __nv_bfloat16*)pB, dscale, out);
}